// round 9
// baseline (speedup 1.0000x reference)
#include <cuda_runtime.h>
#include <cuda_fp16.h>
#include <math.h>
#include <stdint.h>

// RoutingLayer via mma.sync m16n8k16 fp16 (portable PTX for sm_103 target).
// out[B,64] = scatter(softmax(top2(x@w_gate + noise*(softplus(x@w_noise)+0.01))))
// B=32768, D=2048, E=64. Fused GEMM N=128 (0..63 gate, 64..127 noise).
// FP16x2 split: x=h0+h1, (256*w)=h0+h1; h0h0 + h0h1 + h1h0, scaled 2^-8.
// R9: warp tile 32Mx64N, TPB=256, BKC=16 -> ~115 regs -> 16 warps/SM (4/SMSP)
// to feed the full-rate (rt~8) HMMA pipe. A direct from gmem; B cp.async
// double-buffered; epilogue staged once through smem (gate/noise warp-split).

#define KDIM 2048
#define EDIM 64
#define BM   128
#define BKC  16
#define NCHUNK (KDIM / BKC)   // 128
#define TPB  256
#define CP   132              // C staging pitch (floats)

// smem: B double buffer = 2*512 uint4 = 16KB; staging needs 128*CP*4 = 67584
#define BUF_U 512
#define SMEM_BYTES (BM * CP * 4)   // 67584 (>= 2*BUF_U*16 = 16384)

// pre-split weights: [k16 step s(128)][n(128)][tig(4)] uint4 = (b0_h0,b1_h0,b0_h1,b1_h1)
__device__ uint4 g_wb[128 * 128 * 4];   // 1 MB

__device__ __forceinline__ uint32_t pack2(__half lo, __half hi) {
    __half2 h = __halves2half2(lo, hi);
    return *(uint32_t*)&h;
}

__device__ __forceinline__ void mma16(float* c, uint32_t a0, uint32_t a1,
                                      uint32_t a2, uint32_t a3,
                                      uint32_t b0, uint32_t b1) {
    asm volatile(
        "mma.sync.aligned.m16n8k16.row.col.f32.f16.f16.f32 "
        "{%0,%1,%2,%3}, {%4,%5,%6,%7}, {%8,%9}, {%0,%1,%2,%3};"
        : "+f"(c[0]), "+f"(c[1]), "+f"(c[2]), "+f"(c[3])
        : "r"(a0), "r"(a1), "r"(a2), "r"(a3), "r"(b0), "r"(b1));
}

__device__ __forceinline__ uint32_t smem_u32(const void* p) {
    uint32_t a;
    asm("{ .reg .u64 t; cvta.to.shared.u64 t, %1; cvt.u32.u64 %0, t; }" : "=r"(a) : "l"(p));
    return a;
}
#define CP_ASYNC16(dst, src) \
    asm volatile("cp.async.cg.shared.global [%0], [%1], 16;" :: "r"(dst), "l"(src) : "memory")
#define CP_COMMIT() asm volatile("cp.async.commit_group;" ::: "memory")
#define CP_WAIT0()  asm volatile("cp.async.wait_group 0;" ::: "memory")

// ---- prep: split 256*w into fp16 (h0,h1), fragment-native B layout ----
__global__ void prep_w(const float* __restrict__ wg, const float* __restrict__ wn) {
    const int idx = blockIdx.x * blockDim.x + threadIdx.x;  // 0..65535
    const int tig = idx & 3;
    const int n   = (idx >> 2) & 127;
    const int s   = idx >> 9;            // k16 step 0..127
    const int kb  = s * 16;
    const int kk[4] = {kb + 2*tig, kb + 2*tig + 1, kb + 2*tig + 8, kb + 2*tig + 9};
    float v[4];
    #pragma unroll
    for (int j = 0; j < 4; j++)
        v[j] = 256.0f * ((n < 64) ? wg[kk[j] * 64 + n] : wn[kk[j] * 64 + (n - 64)]);
    __half h0[4], h1[4];
    #pragma unroll
    for (int j = 0; j < 4; j++) {
        h0[j] = __float2half_rn(v[j]);
        h1[j] = __float2half_rn(v[j] - __half2float(h0[j]));
    }
    uint4 w4;
    w4.x = pack2(h0[0], h0[1]);
    w4.y = pack2(h0[2], h0[3]);
    w4.z = pack2(h1[0], h1[1]);
    w4.w = pack2(h1[2], h1[3]);
    g_wb[(size_t)(s * 128 + n) * 4 + tig] = w4;
}

// convert 4 raw float2 k-pairs into one mma A fragment (hi + lo)
__device__ __forceinline__ void cvt4(const float2 r0, const float2 r1,
                                     const float2 r2, const float2 r3,
                                     uint32_t* ah, uint32_t* al) {
    const float2 rr[4] = {r0, r1, r2, r3};
    #pragma unroll
    for (int j = 0; j < 4; j++) {
        __half a = __float2half_rn(rr[j].x);
        __half b = __float2half_rn(rr[j].y);
        ah[j] = pack2(a, b);
        al[j] = pack2(__float2half_rn(rr[j].x - __half2float(a)),
                      __float2half_rn(rr[j].y - __half2float(b)));
    }
}

// ---- main ----
__global__ __launch_bounds__(TPB, 2)
void routing_mma(const float* __restrict__ x,
                 const float* __restrict__ nz,
                 float* __restrict__ out)
{
    extern __shared__ uint4 sm4[];
    const int tid = threadIdx.x;
    const int wid = tid >> 5;            // 0..7
    const int lane = tid & 31;
    const int gid = lane >> 2;
    const int tig = lane & 3;
    const int r0 = blockIdx.x * BM;
    const int mb = (wid >> 1) * 32;      // warp rows [mb, mb+32)
    const int nh = (wid & 1) * 64;       // warp n columns [nh, nh+64)

    float c[2][8][4];
    #pragma unroll
    for (int mt = 0; mt < 2; mt++)
        #pragma unroll
        for (int nt = 0; nt < 8; nt++)
            #pragma unroll
            for (int j = 0; j < 4; j++) c[mt][nt][j] = 0.f;

    // A direct-gmem pointers: lane's fragment rows (twin N-half warp hits L1)
    const float* xr[4];
    #pragma unroll
    for (int rr = 0; rr < 4; rr++)
        xr[rr] = x + (size_t)(r0 + mb + gid + 8 * rr) * KDIM + 2 * tig;

    const uint32_t sb = smem_u32(sm4);

    uint32_t ah[8], al[8];   // fragments: mt0 = [0..3], mt1 = [4..7]
    float2 raw[8];           // rr + 4*pair

    // ---- prologue: chunk 0 ----
    {
        #pragma unroll
        for (int rr = 0; rr < 4; rr++) {
            raw[rr]     = *(const float2*)(xr[rr]);
            raw[rr + 4] = *(const float2*)(xr[rr] + 8);
        }
        const uint4* src = g_wb + tid;
        #pragma unroll
        for (int j = 0; j < 2; j++) {
            uint32_t dst = sb + (uint32_t)(j * 256 + tid) * 16u;
            CP_ASYNC16(dst, src + j * 256);
        }
        CP_COMMIT();
        cvt4(raw[0], raw[1], raw[4], raw[5], &ah[0], &al[0]);
        cvt4(raw[2], raw[3], raw[6], raw[7], &ah[4], &al[4]);
        CP_WAIT0();
    }
    __syncthreads();

    int p = 0;
    for (int t = 0; t < NCHUNK; t++) {
        const bool more = (t + 1 < NCHUNK);
        if (more) {
            const int k0 = (t + 1) * BKC;
            #pragma unroll
            for (int rr = 0; rr < 4; rr++) {
                raw[rr]     = *(const float2*)(xr[rr] + k0);
                raw[rr + 4] = *(const float2*)(xr[rr] + k0 + 8);
            }
            const uint4* src = g_wb + (size_t)(t + 1) * 512 + tid;
            const int qb = 1 - p;
            #pragma unroll
            for (int j = 0; j < 2; j++) {
                uint32_t dst = sb + (uint32_t)(qb * BUF_U + j * 256 + tid) * 16u;
                CP_ASYNC16(dst, src + j * 256);
            }
            CP_COMMIT();
        }

        // ---- compute chunk t: B from smem buffer p, A from registers ----
        {
            const uint4* bb = sm4 + p * BUF_U;
            #pragma unroll
            for (int nt = 0; nt < 8; nt++) {
                uint4 Bv = bb[((nh + nt * 8 + gid)) * 4 + tig];
                // dep distance 2 via mt interleave; per-acc order h0h0,h0h1,h1h0
                mma16(c[0][nt], ah[0], ah[1], ah[2], ah[3], Bv.x, Bv.y);
                mma16(c[1][nt], ah[4], ah[5], ah[6], ah[7], Bv.x, Bv.y);
                mma16(c[0][nt], ah[0], ah[1], ah[2], ah[3], Bv.z, Bv.w);
                mma16(c[1][nt], ah[4], ah[5], ah[6], ah[7], Bv.z, Bv.w);
                mma16(c[0][nt], al[0], al[1], al[2], al[3], Bv.x, Bv.y);
                mma16(c[1][nt], al[4], al[5], al[6], al[7], Bv.x, Bv.y);
            }
        }

        if (more) {
            cvt4(raw[0], raw[1], raw[4], raw[5], &ah[0], &al[0]);
            cvt4(raw[2], raw[3], raw[6], raw[7], &ah[4], &al[4]);
            CP_WAIT0();
            __syncthreads();
            p = 1 - p;
        }
    }

    // ---- stage C through smem (gate & noise cols live in different warps) ----
    const float S = 1.0f / 256.0f;
    __syncthreads();
    {
        float* Cs = (float*)sm4;
        #pragma unroll
        for (int mt = 0; mt < 2; mt++) {
            #pragma unroll
            for (int nt = 0; nt < 8; nt++) {
                const int m = mb + mt * 16 + gid;
                const int n = nh + nt * 8 + 2 * tig;
                *(float2*)(Cs + m * CP + n) =
                    make_float2(c[mt][nt][0] * S, c[mt][nt][1] * S);
                *(float2*)(Cs + (m + 8) * CP + n) =
                    make_float2(c[mt][nt][2] * S, c[mt][nt][3] * S);
            }
        }
    }
    __syncthreads();

    // ---- epilogue: one thread per row ----
    if (tid < BM) {
        const int r = tid;
        const int row = r0 + r;
        const float* Cs = (const float*)sm4;
        const float4* nzr = (const float4*)(nz + (size_t)row * EDIM);

        float v1 = -INFINITY, v2 = -INFINITY;
        int i1 = 0x7fffffff, i2 = 0x7fffffff;
        #pragma unroll 4
        for (int e4 = 0; e4 < 16; e4++) {
            float4 z = nzr[e4];
            const float zf[4] = {z.x, z.y, z.z, z.w};
            #pragma unroll
            for (int j = 0; j < 4; j++) {
                const int e = e4 * 4 + j;
                float g = Cs[r * CP + e];
                float s = Cs[r * CP + 64 + e];
                float sp = fmaxf(s, 0.f) + log1pf(expf(-fabsf(s)));
                float v = fmaf(zf[j], sp + 0.01f, g);
                if (v > v1)      { v2 = v1; i2 = i1; v1 = v; i1 = e; }
                else if (v > v2) { v2 = v; i2 = e; }
            }
        }

        float e2 = expf(v2 - v1);
        float denom = 1.f + e2;
        float g1 = 1.f / denom;
        float g2 = e2 / denom;

        float4* orow = (float4*)(out + (size_t)row * EDIM);
        #pragma unroll 4
        for (int e4 = 0; e4 < 16; e4++) {
            float o[4];
            #pragma unroll
            for (int j = 0; j < 4; j++) {
                const int e = e4 * 4 + j;
                o[j] = (e == i1) ? g1 : ((e == i2) ? g2 : 0.f);
            }
            orow[e4] = make_float4(o[0], o[1], o[2], o[3]);
        }
    }
}

extern "C" void kernel_launch(void* const* d_in, const int* in_sizes, int n_in,
                              void* d_out, int out_size)
{
    const float* x  = (const float*)d_in[0];   // [32768, 2048]
    const float* wg = (const float*)d_in[1];   // [2048, 64]
    const float* wn = (const float*)d_in[2];   // [2048, 64]
    const float* nz = (const float*)d_in[3];   // [32768, 64]
    float* out = (float*)d_out;                // [32768, 64]

    prep_w<<<256, 256>>>(wg, wn);

    cudaFuncSetAttribute(routing_mma, cudaFuncAttributeMaxDynamicSharedMemorySize,
                         SMEM_BYTES);
    const int B = in_sizes[0] / KDIM;          // 32768
    routing_mma<<<B / BM, TPB, SMEM_BYTES>>>(x, nz, out);
}

// round 10
// speedup vs baseline: 1.1846x; 1.1846x over previous
#include <cuda_runtime.h>
#include <cuda_fp16.h>
#include <math.h>
#include <stdint.h>

// RoutingLayer via mma.sync m16n8k16 fp16 (portable PTX for sm_103 target).
// out[B,64] = scatter(softmax(top2(x@w_gate + noise*(softplus(x@w_noise)+0.01))))
// B=32768, D=2048, E=64. Fused GEMM N=128 (0..63 gate, 64..127 noise).
// FP16x2 split: x=h0+h1, (256*w)=h0+h1; h0h0 + h0h1 + h1h0, scaled 2^-8.
// R10 = R8 shape (TPB=128, warp 32Mx128N, BKC=32, grid 256) with:
//  - nt-pair MMA interleave: accumulator dep distance 4 (was 2)
//  - 3-stage cp.async B ring: barrier arrives with a full chunk of slack
//  - ~215 regs -> scheduler headroom for B-LDS hoisting

#define KDIM 2048
#define EDIM 64
#define BM   128
#define BKC  32
#define NCHUNK (KDIM / BKC)   // 64
#define TPB  128
#define NBUF 3

// smem: B ring. Per buffer 1024 16B-units: unit = s*512 + n*4 + tig
#define BUF_U 1024
#define SMEM_BYTES (NBUF * BUF_U * 16)   // 49152

// pre-split weights: [k16 step s(128)][n(128)][tig(4)] uint4 = (b0_h0,b1_h0,b0_h1,b1_h1)
__device__ uint4 g_wb[128 * 128 * 4];   // 1 MB

__device__ __forceinline__ uint32_t pack2(__half lo, __half hi) {
    __half2 h = __halves2half2(lo, hi);
    return *(uint32_t*)&h;
}

__device__ __forceinline__ void mma16(float* c, uint32_t a0, uint32_t a1,
                                      uint32_t a2, uint32_t a3,
                                      uint32_t b0, uint32_t b1) {
    asm volatile(
        "mma.sync.aligned.m16n8k16.row.col.f32.f16.f16.f32 "
        "{%0,%1,%2,%3}, {%4,%5,%6,%7}, {%8,%9}, {%0,%1,%2,%3};"
        : "+f"(c[0]), "+f"(c[1]), "+f"(c[2]), "+f"(c[3])
        : "r"(a0), "r"(a1), "r"(a2), "r"(a3), "r"(b0), "r"(b1));
}

__device__ __forceinline__ uint32_t smem_u32(const void* p) {
    uint32_t a;
    asm("{ .reg .u64 t; cvta.to.shared.u64 t, %1; cvt.u32.u64 %0, t; }" : "=r"(a) : "l"(p));
    return a;
}
#define CP_ASYNC16(dst, src) \
    asm volatile("cp.async.cg.shared.global [%0], [%1], 16;" :: "r"(dst), "l"(src) : "memory")
#define CP_COMMIT() asm volatile("cp.async.commit_group;" ::: "memory")
#define CP_WAIT1()  asm volatile("cp.async.wait_group 1;" ::: "memory")

// ---- prep: split 256*w into fp16 (h0,h1), fragment-native B layout ----
__global__ void prep_w(const float* __restrict__ wg, const float* __restrict__ wn) {
    const int idx = blockIdx.x * blockDim.x + threadIdx.x;  // 0..65535
    const int tig = idx & 3;
    const int n   = (idx >> 2) & 127;
    const int s   = idx >> 9;            // k16 step 0..127
    const int kb  = s * 16;
    const int kk[4] = {kb + 2*tig, kb + 2*tig + 1, kb + 2*tig + 8, kb + 2*tig + 9};
    float v[4];
    #pragma unroll
    for (int j = 0; j < 4; j++)
        v[j] = 256.0f * ((n < 64) ? wg[kk[j] * 64 + n] : wn[kk[j] * 64 + (n - 64)]);
    __half h0[4], h1[4];
    #pragma unroll
    for (int j = 0; j < 4; j++) {
        h0[j] = __float2half_rn(v[j]);
        h1[j] = __float2half_rn(v[j] - __half2float(h0[j]));
    }
    uint4 w4;
    w4.x = pack2(h0[0], h0[1]);
    w4.y = pack2(h0[2], h0[3]);
    w4.z = pack2(h1[0], h1[1]);
    w4.w = pack2(h1[2], h1[3]);
    g_wb[(size_t)(s * 128 + n) * 4 + tig] = w4;
}

// convert 4 raw float2 k-pairs into one mma A fragment (hi + lo)
__device__ __forceinline__ void cvt4(const float2 r0, const float2 r1,
                                     const float2 r2, const float2 r3,
                                     uint32_t* ah, uint32_t* al) {
    const float2 rr[4] = {r0, r1, r2, r3};
    #pragma unroll
    for (int j = 0; j < 4; j++) {
        __half a = __float2half_rn(rr[j].x);
        __half b = __float2half_rn(rr[j].y);
        ah[j] = pack2(a, b);
        al[j] = pack2(__float2half_rn(rr[j].x - __half2float(a)),
                      __float2half_rn(rr[j].y - __half2float(b)));
    }
}

__device__ __forceinline__ void load_raw(const float* const* xr, int k0, float2* raw) {
    #pragma unroll
    for (int s = 0; s < 2; s++)
        #pragma unroll
        for (int rr = 0; rr < 4; rr++) {
            raw[s * 8 + rr]     = *(const float2*)(xr[rr] + k0 + s * 16);
            raw[s * 8 + rr + 4] = *(const float2*)(xr[rr] + k0 + s * 16 + 8);
        }
}

__device__ __forceinline__ void cvt_all(const float2* raw, uint32_t (*ah)[8],
                                        uint32_t (*al)[8]) {
    #pragma unroll
    for (int s = 0; s < 2; s++) {
        cvt4(raw[s*8+0], raw[s*8+1], raw[s*8+4], raw[s*8+5], &ah[s][0], &al[s][0]);
        cvt4(raw[s*8+2], raw[s*8+3], raw[s*8+6], raw[s*8+7], &ah[s][4], &al[s][4]);
    }
}

__device__ __forceinline__ void issue_b(uint32_t sb, int buf, int chunk) {
    const uint4* src = g_wb + (size_t)chunk * 1024 + threadIdx.x;
    #pragma unroll
    for (int j = 0; j < 8; j++) {
        uint32_t dst = sb + (uint32_t)(buf * BUF_U + j * 128 + threadIdx.x) * 16u;
        CP_ASYNC16(dst, src + j * 128);
    }
    CP_COMMIT();
}

// ---- main ----
__global__ __launch_bounds__(TPB, 2)
void routing_mma(const float* __restrict__ x,
                 const float* __restrict__ nz,
                 float* __restrict__ out)
{
    extern __shared__ uint4 sm4[];
    const int tid = threadIdx.x;
    const int wid = tid >> 5;            // 0..3
    const int lane = tid & 31;
    const int gid = lane >> 2;
    const int tig = lane & 3;
    const int r0 = blockIdx.x * BM;
    const int m0 = wid * 32;             // warp rows [m0, m0+32)

    float c[2][16][4];
    #pragma unroll
    for (int mt = 0; mt < 2; mt++)
        #pragma unroll
        for (int nt = 0; nt < 16; nt++)
            #pragma unroll
            for (int j = 0; j < 4; j++) c[mt][nt][j] = 0.f;

    // A direct-gmem pointers for this lane's fragment rows
    const float* xr[4];
    #pragma unroll
    for (int rr = 0; rr < 4; rr++)
        xr[rr] = x + (size_t)(r0 + m0 + gid + 8 * rr) * KDIM + 2 * tig;

    const uint32_t sb = smem_u32(sm4);

    uint32_t ah[2][8], al[2][8];   // current chunk fragments (s half; mt0:0-3, mt1:4-7)
    float2 raw[16];                // prefetched next-chunk raw pairs

    // ---- prologue: B chunks 0,1 in flight; A chunk 0 converted ----
    load_raw(xr, 0, raw);
    issue_b(sb, 0, 0);
    issue_b(sb, 1, 1);
    cvt_all(raw, ah, al);

    for (int t = 0; t < NCHUNK; t++) {
        CP_WAIT1();              // chunk t resident (chunk t+1 may still fly)
        __syncthreads();         // visibility + all warps done with buf[(t-1)%3]
        if (t + 2 < NCHUNK) issue_b(sb, (t + 2) % NBUF, t + 2);
        if (t + 1 < NCHUNK) load_raw(xr, (t + 1) * BKC, raw);

        // ---- compute chunk t: B from buf[t%3], A from registers ----
        {
            const uint4* buf = sm4 + (t % NBUF) * BUF_U;
            #pragma unroll
            for (int s = 0; s < 2; s++) {
                const uint4* bb = buf + s * 512;
                const uint32_t* h = ah[s];
                const uint32_t* l = al[s];
                #pragma unroll
                for (int nt = 0; nt < 16; nt += 2) {
                    uint4 B0 = bb[((nt)     * 8 + gid) * 4 + tig];
                    uint4 B1 = bb[((nt + 1) * 8 + gid) * 4 + tig];
                    // dep distance 4; per-acc term order h0h0, h0h1, h1h0
                    mma16(c[0][nt],   h[0], h[1], h[2], h[3], B0.x, B0.y);
                    mma16(c[1][nt],   h[4], h[5], h[6], h[7], B0.x, B0.y);
                    mma16(c[0][nt+1], h[0], h[1], h[2], h[3], B1.x, B1.y);
                    mma16(c[1][nt+1], h[4], h[5], h[6], h[7], B1.x, B1.y);
                    mma16(c[0][nt],   h[0], h[1], h[2], h[3], B0.z, B0.w);
                    mma16(c[1][nt],   h[4], h[5], h[6], h[7], B0.z, B0.w);
                    mma16(c[0][nt+1], h[0], h[1], h[2], h[3], B1.z, B1.w);
                    mma16(c[1][nt+1], h[4], h[5], h[6], h[7], B1.z, B1.w);
                    mma16(c[0][nt],   l[0], l[1], l[2], l[3], B0.x, B0.y);
                    mma16(c[1][nt],   l[4], l[5], l[6], l[7], B0.x, B0.y);
                    mma16(c[0][nt+1], l[0], l[1], l[2], l[3], B1.x, B1.y);
                    mma16(c[1][nt+1], l[4], l[5], l[6], l[7], B1.x, B1.y);
                }
            }
        }

        if (t + 1 < NCHUNK) cvt_all(raw, ah, al);   // fragments for t+1
    }

    // ---- epilogue: 4 rows per lane (gid+8*hh), intra-quad top-2 ----
    const float S = 1.0f / 256.0f;   // undo weight pre-scale (exact)
    float v1[4] = {-INFINITY, -INFINITY, -INFINITY, -INFINITY};
    float v2[4] = {-INFINITY, -INFINITY, -INFINITY, -INFINITY};
    int   i1[4] = {0x7fffffff, 0x7fffffff, 0x7fffffff, 0x7fffffff};
    int   i2[4] = {0x7fffffff, 0x7fffffff, 0x7fffffff, 0x7fffffff};

    #pragma unroll
    for (int hh = 0; hh < 4; hh++) {
        const int row = r0 + m0 + gid + 8 * hh;
        const int mt = hh >> 1;
        const int jb = (hh & 1) * 2;
        #pragma unroll
        for (int nt = 0; nt < 8; nt++) {
            const int e0 = nt * 8 + 2 * tig;
            float2 z = *(const float2*)(nz + (size_t)row * EDIM + e0);
            const float zf[2] = {z.x, z.y};
            #pragma unroll
            for (int j = 0; j < 2; j++) {
                float g = c[mt][nt][jb + j] * S;
                float s = c[mt][nt + 8][jb + j] * S;
                float sp = fmaxf(s, 0.f) + log1pf(expf(-fabsf(s)));
                float v = fmaf(zf[j], sp + 0.01f, g);
                const int e = e0 + j;
                if (v > v1[hh])      { v2[hh] = v1[hh]; i2[hh] = i1[hh]; v1[hh] = v; i1[hh] = e; }
                else if (v > v2[hh]) { v2[hh] = v; i2[hh] = e; }
            }
        }
    }

    #pragma unroll
    for (int hh = 0; hh < 4; hh++) {
        #pragma unroll
        for (int off = 1; off < 4; off <<= 1) {
            float ov1 = __shfl_xor_sync(0xffffffffu, v1[hh], off);
            int   oi1 = __shfl_xor_sync(0xffffffffu, i1[hh], off);
            float ov2 = __shfl_xor_sync(0xffffffffu, v2[hh], off);
            int   oi2 = __shfl_xor_sync(0xffffffffu, i2[hh], off);
            bool firstMine = (v1[hh] > ov1) || (v1[hh] == ov1 && i1[hh] < oi1);
            float nv1, nv2; int ni1, ni2;
            if (firstMine) {
                nv1 = v1[hh]; ni1 = i1[hh];
                bool s2 = (v2[hh] > ov1) || (v2[hh] == ov1 && i2[hh] < oi1);
                nv2 = s2 ? v2[hh] : ov1; ni2 = s2 ? i2[hh] : oi1;
            } else {
                nv1 = ov1; ni1 = oi1;
                bool s2 = (ov2 > v1[hh]) || (ov2 == v1[hh] && oi2 < i1[hh]);
                nv2 = s2 ? ov2 : v1[hh]; ni2 = s2 ? oi2 : i1[hh];
            }
            v1[hh] = nv1; i1[hh] = ni1; v2[hh] = nv2; i2[hh] = ni2;
        }
    }

    #pragma unroll
    for (int hh = 0; hh < 4; hh++) {
        float e2 = expf(v2[hh] - v1[hh]);
        float denom = 1.f + e2;
        float g1 = 1.f / denom;
        float g2 = e2 / denom;
        const int row = r0 + m0 + gid + 8 * hh;
        #pragma unroll
        for (int nt = 0; nt < 8; nt++) {
            const int e0 = nt * 8 + 2 * tig;
            float2 o;
            o.x = (e0 == i1[hh]) ? g1 : ((e0 == i2[hh]) ? g2 : 0.f);
            o.y = (e0 + 1 == i1[hh]) ? g1 : ((e0 + 1 == i2[hh]) ? g2 : 0.f);
            *(float2*)(out + (size_t)row * EDIM + e0) = o;
        }
    }
}

extern "C" void kernel_launch(void* const* d_in, const int* in_sizes, int n_in,
                              void* d_out, int out_size)
{
    const float* x  = (const float*)d_in[0];   // [32768, 2048]
    const float* wg = (const float*)d_in[1];   // [2048, 64]
    const float* wn = (const float*)d_in[2];   // [2048, 64]
    const float* nz = (const float*)d_in[3];   // [32768, 64]
    float* out = (float*)d_out;                // [32768, 64]

    prep_w<<<256, 256>>>(wg, wn);

    cudaFuncSetAttribute(routing_mma, cudaFuncAttributeMaxDynamicSharedMemorySize,
                         SMEM_BYTES);
    const int B = in_sizes[0] / KDIM;          // 32768
    routing_mma<<<B / BM, TPB, SMEM_BYTES>>>(x, nz, out);
}